// round 17
// baseline (speedup 1.0000x reference)
#include <cuda_runtime.h>
#include <cuda_bf16.h>
#include <cstdint>
#include <stdint.h>
#include <math.h>

// Problem constants (fixed by the dataset)
#define B_ROWS 65536
#define DIM    256
#define KF     60
#define KC     40
#define KPAD   64
#define TILE_R 64
#define NTILES (B_ROWS / TILE_R)   // 1024
#define NBLOCKS 148
#define MTHREADS 512
#define ALPHA_C 0.5f

// bf16 strides (elements); 264*2B=528B=132 words ≡ 4 (mod 32) -> ldmatrix conflict-free
#define SAF 264
#define SAC 520            // 520*2B=1040B=260 words ≡ 4 (mod 32)

// ---------------- device scratch ----------------
__device__ float g_CnF[KF * DIM];
__device__ float g_CnV[KC * DIM];
__device__ float g_CnT[KC * DIM];
__device__ __align__(16) __nv_bfloat16 g_bCF[KPAD * SAF];
__device__ __align__(16) __nv_bfloat16 g_bCC[KPAD * SAC];
// Statically initialized; only ever cleared to 0 by the identity check. Inputs
// are identical across graph replays, so the steady state is deterministic.
__device__ int g_flagF = 1, g_flagV = 1, g_flagT = 1;
__device__ double g_sum;           // zeroed by setup_all each launch
__device__ unsigned g_count = 0;   // reset by the last finishing block

// ---------------- smem layout (bytes) ----------------
#define SZ_CF (KPAD * SAF * 2)          // 33792
#define SZ_CC (KPAD * SAC * 2)          // 66560
#define OFF_CF   0
#define OFF_CC   (OFF_CF + SZ_CF)       // 33792
#define OFF_AF   (OFF_CC + SZ_CC)       // 100352
#define OFF_AC   (OFF_AF + SZ_CF)       // 134144
#define OFF_CFV  (OFF_AC + SZ_CC)       // 200704
#define OFF_CFI  (OFF_CFV + 1024)
#define OFF_CCV  (OFF_CFI + 1024)
#define OFF_CCI  (OFF_CCV + 1024)
#define OFF_SKF  (OFF_CCI + 1024)
#define OFF_SKC  (OFF_SKF + 256)
#define OFF_SCF  (OFF_SKC + 256)
#define OFF_SCC  (OFF_SCF + 256)
#define OFF_CMB  (OFF_SCC + 256)
#define OFF_RF   (OFF_CMB + 256)
#define OFF_RV   (OFF_RF + 256)
#define OFF_RT   (OFF_RV + 256)
#define OFF_RED  (OFF_RT + 256)
#define SMEM_TOTAL (OFF_RED + MTHREADS * 8)   // 210944

// ---------------- kernel 1: setup codebooks + identity check (merged) ----------------
__global__ void setup_all(const float* __restrict__ bookF,
                          const float* __restrict__ centV,
                          const float* __restrict__ centT,
                          const float* __restrict__ Wv,
                          const float* __restrict__ Wt,
                          const float* __restrict__ Wf) {
    int b = blockIdx.x;
    int t = threadIdx.x;
    if (b == 0 && t == 0) g_sum = 0.0;
    if (b >= 192) {                       // identity check: 768 blocks
        int idx = (b - 192) * 256 + t;    // < 3*65536
        int w = idx >> 16;
        int e = idx & 65535;
        const float* W = (w == 0) ? Wv : (w == 1) ? Wt : Wf;
        float expv = ((e >> 8) == (e & 255)) ? 1.f : 0.f;
        if (fabsf(W[e] - expv) > 1e-6f) {
            if (w == 0) atomicExch(&g_flagV, 0);
            else if (w == 1) atomicExch(&g_flagT, 0);
            else atomicExch(&g_flagF, 0);
        }
        return;
    }
    int book = b >> 6;
    int k = b & 63;
    if (book == 0) {
        if (k >= KF) {
            g_bCF[k * SAF + t] = __float2bfloat16(0.f);
            if (t < SAF - DIM) g_bCF[k * SAF + DIM + t] = __float2bfloat16(0.f);
            return;
        }
        float x = bookF[k * DIM + t];
        __shared__ float red[256];
        red[t] = x * x; __syncthreads();
        for (int s = 128; s > 0; s >>= 1) { if (t < s) red[t] += red[t + s]; __syncthreads(); }
        float v = x * rsqrtf(fmaxf(red[0], 1e-24f));
        g_CnF[k * DIM + t] = v;
        g_bCF[k * SAF + t] = __float2bfloat16(v);
        if (t < SAF - DIM) g_bCF[k * SAF + DIM + t] = __float2bfloat16(0.f);
    } else if (book == 1) {
        if (k >= KC) {
            g_bCC[k * SAC + t] = __float2bfloat16(0.f);
            if (t < SAC - 2 * DIM) g_bCC[k * SAC + 2 * DIM + t] = __float2bfloat16(0.f);
            return;
        }
        float x = centV[k * DIM + t];
        __shared__ float red[256];
        red[t] = x * x; __syncthreads();
        for (int s = 128; s > 0; s >>= 1) { if (t < s) red[t] += red[t + s]; __syncthreads(); }
        float v = x * rsqrtf(fmaxf(red[0], 1e-24f));
        g_CnV[k * DIM + t] = v;
        g_bCC[k * SAC + t] = __float2bfloat16(ALPHA_C * v);
        if (t < SAC - 2 * DIM) g_bCC[k * SAC + 2 * DIM + t] = __float2bfloat16(0.f);
    } else {
        if (k >= KC) {
            g_bCC[k * SAC + DIM + t] = __float2bfloat16(0.f);
            return;
        }
        float x = centT[k * DIM + t];
        __shared__ float red[256];
        red[t] = x * x; __syncthreads();
        for (int s = 128; s > 0; s >>= 1) { if (t < s) red[t] += red[t + s]; __syncthreads(); }
        float v = x * rsqrtf(fmaxf(red[0], 1e-24f));
        g_CnT[k * DIM + t] = v;
        g_bCC[k * SAC + DIM + t] = __float2bfloat16((1.f - ALPHA_C) * v);
    }
}

// ---------------- PTX helpers ----------------
__device__ __forceinline__ unsigned smem_u32(const void* p) {
    return (unsigned)__cvta_generic_to_shared(p);
}
__device__ __forceinline__ void ldsm_x4(unsigned addr, unsigned& r0, unsigned& r1,
                                        unsigned& r2, unsigned& r3) {
    asm volatile("ldmatrix.sync.aligned.m8n8.x4.shared.b16 {%0,%1,%2,%3}, [%4];\n"
                 : "=r"(r0), "=r"(r1), "=r"(r2), "=r"(r3) : "r"(addr));
}
__device__ __forceinline__ void ldsm_x2(unsigned addr, unsigned& r0, unsigned& r1) {
    asm volatile("ldmatrix.sync.aligned.m8n8.x2.shared.b16 {%0,%1}, [%2];\n"
                 : "=r"(r0), "=r"(r1) : "r"(addr));
}
__device__ __forceinline__ void mma_bf16(float c[4], unsigned a0, unsigned a1,
                                         unsigned a2, unsigned a3,
                                         unsigned b0, unsigned b1) {
    asm volatile("mma.sync.aligned.m16n8k16.row.col.f32.bf16.bf16.f32 "
                 "{%0,%1,%2,%3},{%4,%5,%6,%7},{%8,%9},{%0,%1,%2,%3};\n"
                 : "+f"(c[0]), "+f"(c[1]), "+f"(c[2]), "+f"(c[3])
                 : "r"(a0), "r"(a1), "r"(a2), "r"(a3), "r"(b0), "r"(b1));
}
__device__ __forceinline__ unsigned pack2(float a, float b) {
    __nv_bfloat162 t = __floats2bfloat162_rn(a, b);
    return *reinterpret_cast<unsigned*>(&t);
}

// ---------------- tile load / raw pack (512 threads: r=tid>>3, k8=tid&7) ----------------
__device__ __forceinline__ void ld_rows(const float* __restrict__ src, int tileRow,
                                        int r, int k8, float4 v[8]) {
    const float4* row4 = (const float4*)src + (size_t)(tileRow + r) * (DIM / 4);
    #pragma unroll
    for (int it = 0; it < 8; ++it) v[it] = row4[k8 + it * 8];
}

// raw bf16 pack (no normalization on the STS path) + rinv side-computation
__device__ __forceinline__ void pack_raw(const float4 v[8], __nv_bfloat16* sA,
                                         int colOff, int stride, int r, int k8,
                                         float* rinv) {
    float ss = 0.f;
    #pragma unroll
    for (int it = 0; it < 8; ++it) {
        int f = k8 + it * 8;
        uint2 p;
        p.x = pack2(v[it].x, v[it].y);
        p.y = pack2(v[it].z, v[it].w);
        *(uint2*)((char*)sA + ((size_t)r * stride + colOff + f * 4) * 2) = p;
        ss += v[it].x * v[it].x + v[it].y * v[it].y + v[it].z * v[it].z + v[it].w * v[it].w;
    }
    ss += __shfl_xor_sync(0xffffffffu, ss, 4);
    ss += __shfl_xor_sync(0xffffffffu, ss, 2);
    ss += __shfl_xor_sync(0xffffffffu, ss, 1);
    if (k8 == 0) rinv[r] = rsqrtf(fmaxf(ss, 1e-24f));
}

// partial dot of register half-row against a bf16 code row in smem (no reduction)
__device__ __forceinline__ void dot_part(const float4 v[8],
                                         const __nv_bfloat16* __restrict__ codeRow,
                                         int k8, float& d, float& ss) {
    d = 0.f; ss = 0.f;
    #pragma unroll
    for (int it = 0; it < 8; ++it) {
        int f = k8 + it * 8;
        uint2 cw = *(const uint2*)(codeRow + 4 * f);
        __nv_bfloat162 c01 = *reinterpret_cast<__nv_bfloat162*>(&cw.x);
        __nv_bfloat162 c23 = *reinterpret_cast<__nv_bfloat162*>(&cw.y);
        float2 f01 = __bfloat1622float2(c01);
        float2 f23 = __bfloat1622float2(c23);
        d  += v[it].x * f01.x + v[it].y * f01.y + v[it].z * f23.x + v[it].w * f23.y;
        ss += v[it].x * v[it].x + v[it].y * v[it].y + v[it].z * v[it].z + v[it].w * v[it].w;
    }
}

// ---------------- F GEMM (raw A; argmax scale-invariant) ----------------
__device__ __forceinline__ void mma_passF(const __nv_bfloat16* sA, const __nv_bfloat16* sB,
                                          float* candV, int* candI, int w, int lane) {
    int r0 = (w >> 2) * 16;
    int c0 = (w & 3) * 16;
    int li = lane & 7;
    int sub = lane >> 3;
    unsigned aAddr = smem_u32(sA) + ((r0 + (sub & 1) * 8 + li) * SAF + (sub >> 1) * 8) * 2;
    int bsub = (lane >> 3) & 1;
    unsigned bAddr0 = smem_u32(sB) + ((c0 + li) * SAF + bsub * 8) * 2;
    unsigned bAddr1 = bAddr0 + 8 * SAF * 2;
    float acc0[4] = {0.f, 0.f, 0.f, 0.f};
    float acc1[4] = {0.f, 0.f, 0.f, 0.f};
    #pragma unroll
    for (int ks = 0; ks < DIM / 16; ++ks) {
        unsigned a0, a1, a2, a3, b0, b1, b2, b3;
        ldsm_x4(aAddr + ks * 32, a0, a1, a2, a3);
        ldsm_x2(bAddr0 + ks * 32, b0, b1);
        ldsm_x2(bAddr1 + ks * 32, b2, b3);
        mma_bf16(acc0, a0, a1, a2, a3, b0, b1);
        mma_bf16(acc1, a0, a1, a2, a3, b2, b3);
    }
    #pragma unroll
    for (int h = 0; h < 2; ++h) {
        int row = r0 + (lane >> 2) + h * 8;
        float bv = -1e30f; int bi = -1;
        #pragma unroll
        for (int t = 0; t < 2; ++t) {
            #pragma unroll
            for (int q = 0; q < 2; ++q) {
                int col = c0 + t * 8 + (lane & 3) * 2 + q;
                float v = (t ? acc1 : acc0)[h * 2 + q];
                if (col < KF && v > bv) { bv = v; bi = col; }
            }
        }
        #pragma unroll
        for (int o = 1; o < 4; o <<= 1) {
            float ov = __shfl_xor_sync(0xffffffffu, bv, o);
            int   oi = __shfl_xor_sync(0xffffffffu, bi, o);
            if (ov > bv) { bv = ov; bi = oi; }
        }
        if ((lane & 3) == 0) {
            candV[row * 4 + (w & 3)] = bv;
            candI[row * 4 + (w & 3)] = bi;
        }
    }
}

// ---------------- cross GEMM: raw A, split accumulators, rinv-combined epilogue ----------------
__device__ __forceinline__ void mma_passC(const __nv_bfloat16* sA, const __nv_bfloat16* sB,
                                          const float* rinvV, const float* rinvT,
                                          float* candV, int* candI, int w, int lane) {
    int r0 = (w >> 2) * 16;
    int c0 = (w & 3) * 16;
    if (c0 >= KC) {              // columns 48..63 are all padding for KC=40
        if ((lane & 3) == 0) {
            int row = r0 + (lane >> 2);
            candV[row * 4 + (w & 3)] = -1e30f;       candI[row * 4 + (w & 3)] = 0;
            candV[(row + 8) * 4 + (w & 3)] = -1e30f; candI[(row + 8) * 4 + (w & 3)] = 0;
        }
        return;
    }
    int li = lane & 7;
    int sub = lane >> 3;
    unsigned aAddr = smem_u32(sA) + ((r0 + (sub & 1) * 8 + li) * SAC + (sub >> 1) * 8) * 2;
    int bsub = (lane >> 3) & 1;
    unsigned bAddr0 = smem_u32(sB) + ((c0 + li) * SAC + bsub * 8) * 2;
    unsigned bAddr1 = bAddr0 + 8 * SAC * 2;
    float accV0[4] = {0.f, 0.f, 0.f, 0.f};
    float accV1[4] = {0.f, 0.f, 0.f, 0.f};
    float accT0[4] = {0.f, 0.f, 0.f, 0.f};
    float accT1[4] = {0.f, 0.f, 0.f, 0.f};
    #pragma unroll
    for (int ks = 0; ks < 2 * DIM / 16; ++ks) {
        unsigned a0, a1, a2, a3, b0, b1, b2, b3;
        ldsm_x4(aAddr + ks * 32, a0, a1, a2, a3);
        ldsm_x2(bAddr0 + ks * 32, b0, b1);
        ldsm_x2(bAddr1 + ks * 32, b2, b3);
        if (ks < DIM / 16) {
            mma_bf16(accV0, a0, a1, a2, a3, b0, b1);
            mma_bf16(accV1, a0, a1, a2, a3, b2, b3);
        } else {
            mma_bf16(accT0, a0, a1, a2, a3, b0, b1);
            mma_bf16(accT1, a0, a1, a2, a3, b2, b3);
        }
    }
    #pragma unroll
    for (int h = 0; h < 2; ++h) {
        int row = r0 + (lane >> 2) + h * 8;
        float rv = rinvV[row];
        float rt = rinvT[row];
        float bv = -1e30f; int bi = -1;
        #pragma unroll
        for (int t = 0; t < 2; ++t) {
            #pragma unroll
            for (int q = 0; q < 2; ++q) {
                int col = c0 + t * 8 + (lane & 3) * 2 + q;
                float v = (t ? accV1 : accV0)[h * 2 + q] * rv
                        + (t ? accT1 : accT0)[h * 2 + q] * rt;
                if (col < KC && v > bv) { bv = v; bi = col; }
            }
        }
        #pragma unroll
        for (int o = 1; o < 4; o <<= 1) {
            float ov = __shfl_xor_sync(0xffffffffu, bv, o);
            int   oi = __shfl_xor_sync(0xffffffffu, bi, o);
            if (ov > bv) { bv = ov; bi = oi; }
        }
        if ((lane & 3) == 0) {
            candV[row * 4 + (w & 3)] = bv;
            candI[row * 4 + (w & 3)] = bi;
        }
    }
}

// slow-path per-row commit: c = || normalize(x) @ W^T - c_sel ||^2, exact fp32.
// Never taken when all W are identity; correctness fallback only.
__device__ float slow_commit(const float* __restrict__ x, const float* __restrict__ W,
                             const float* __restrict__ csel, int lane) {
    float ss = 0.f;
    for (int e = lane; e < DIM; e += 32) { float v = x[e]; ss += v * v; }
    #pragma unroll
    for (int o = 16; o; o >>= 1) ss += __shfl_xor_sync(0xffffffffu, ss, o);
    float inv = rsqrtf(fmaxf(ss, 1e-24f));
    float c = 0.f;
    for (int a = lane; a < DIM; a += 32) {
        float y = 0.f;
        for (int bb = 0; bb < DIM; ++bb) y += W[a * DIM + bb] * x[bb];
        float d = y * inv - csel[a];
        c += d * d;
    }
    #pragma unroll
    for (int o = 16; o; o >>= 1) c += __shfl_xor_sync(0xffffffffu, c, o);
    return c;
}

__global__ __launch_bounds__(MTHREADS, 1)
void main_kernel(const float* __restrict__ gt_v, const float* __restrict__ gt_t,
                 const float* __restrict__ gt_f, const float* __restrict__ gs_v,
                 const float* __restrict__ gs_t, const float* __restrict__ gs_f,
                 const float* __restrict__ W_v, const float* __restrict__ W_t,
                 const float* __restrict__ W_f, float* __restrict__ out) {
    extern __shared__ char smem_raw[];
    __nv_bfloat16* sCF = (__nv_bfloat16*)(smem_raw + OFF_CF);
    __nv_bfloat16* sCC = (__nv_bfloat16*)(smem_raw + OFF_CC);
    __nv_bfloat16* sAF = (__nv_bfloat16*)(smem_raw + OFF_AF);
    __nv_bfloat16* sAC = (__nv_bfloat16*)(smem_raw + OFF_AC);
    float*  candFV = (float*)(smem_raw + OFF_CFV);
    int*    candFI = (int*)  (smem_raw + OFF_CFI);
    float*  candCV = (float*)(smem_raw + OFF_CCV);
    int*    candCI = (int*)  (smem_raw + OFF_CCI);
    int*    skf    = (int*)  (smem_raw + OFF_SKF);
    int*    skc    = (int*)  (smem_raw + OFF_SKC);
    float*  scostF = (float*)(smem_raw + OFF_SCF);
    float*  scostC = (float*)(smem_raw + OFF_SCC);
    float*  cmBuf  = (float*)(smem_raw + OFF_CMB);
    float*  rF     = (float*)(smem_raw + OFF_RF);
    float*  rV     = (float*)(smem_raw + OFF_RV);
    float*  rT     = (float*)(smem_raw + OFF_RT);
    double* red    = (double*)(smem_raw + OFF_RED);

    int tid = threadIdx.x;
    int w = tid >> 5, lane = tid & 31;
    int r  = tid >> 3;          // 0..63 row within tile
    int k8 = tid & 7;

    // ---- load codebooks once (persistent) ----
    {
        const uint4* s1 = (const uint4*)g_bCF; uint4* d1 = (uint4*)sCF;
        for (int i = tid; i < SZ_CF / 16; i += MTHREADS) d1[i] = s1[i];
        const uint4* s2 = (const uint4*)g_bCC; uint4* d2 = (uint4*)sCC;
        for (int i = tid; i < SZ_CC / 16; i += MTHREADS) d2[i] = s2[i];
    }
    int fF = g_flagF, fV = g_flagV, fT = g_flagT;
    bool fast = (fF & fV & fT) != 0;
    double accRow = 0.0;

    float4 X[8], Y[8];
    int tile = blockIdx.x;
    if (tile < NTILES) {                 // prologue loads: gt_f -> Y, gt_v -> X
        ld_rows(gt_f, tile * TILE_R, r, k8, Y);
        ld_rows(gt_v, tile * TILE_R, r, k8, X);
    }

    for (; tile < NTILES; tile += NBLOCKS) {
        int tileRow = tile * TILE_R;

        // ---- pack gt (raw); gs_f/gs_v loads go in flight for the MMA phase ----
        pack_raw(Y, sAF, 0, SAF, r, k8, rF);      // gt_f
        ld_rows(gt_t, tileRow, r, k8, Y);
        pack_raw(X, sAC, 0, SAC, r, k8, rV);      // gt_v
        ld_rows(gs_f, tileRow, r, k8, X);
        pack_raw(Y, sAC, DIM, SAC, r, k8, rT);    // gt_t
        ld_rows(gs_v, tileRow, r, k8, Y);
        __syncthreads();

        mma_passF(sAF, sCF, candFV, candFI, w, lane);
        mma_passC(sAC, sCC, rV, rT, candCV, candCI, w, lane);
        __syncthreads();

        // ---- final per-row argmax ----
        if (tid < TILE_R) {
            float bv = -1e30f; int bi = 0;
            #pragma unroll
            for (int t = 0; t < 4; ++t) {
                float v = candFV[tid * 4 + t];
                if (v > bv) { bv = v; bi = candFI[tid * 4 + t]; }
            }
            skf[tid] = bi;
            scostF[tid] = fmaxf(2.f - 2.f * bv * rF[tid], 0.f);
        } else if (tid < 2 * TILE_R) {
            int rr = tid - TILE_R;
            float bv = -1e30f; int bi = 0;
            #pragma unroll
            for (int t = 0; t < 4; ++t) {
                float v = candCV[rr * 4 + t];
                if (v > bv) { bv = v; bi = candCI[rr * 4 + t]; }
            }
            skc[rr] = bi;
            scostC[rr] = fmaxf(2.f - 2.f * bv, 0.f);
        }
        __syncthreads();

        int nt = tile + NBLOCKS;
        bool more = nt < NTILES;
        if (fast) {
            // ---- gs commit: partial dots first (independent chains), then one
            //      batched shfl reduction block; prefetches interleaved ----
            int jf = skf[r], jc = skc[r];
            float df, sf, dv, sv, dt, st;
            dot_part(X, sCF + (size_t)jf * SAF, k8, df, sf);        // gs_f . c_f
            ld_rows(gs_t, tileRow, r, k8, X);                       // X := gs_t
            dot_part(Y, sCC + (size_t)jc * SAC, k8, dv, sv);        // gs_v . (a*cv)
            if (more) ld_rows(gt_f, nt * TILE_R, r, k8, Y);         // Y := next gt_f
            dot_part(X, sCC + (size_t)jc * SAC + DIM, k8, dt, st);  // gs_t . ((1-a)*ct)
            if (more) ld_rows(gt_v, nt * TILE_R, r, k8, X);         // X := next gt_v
            #pragma unroll
            for (int o = 4; o; o >>= 1) {
                df += __shfl_xor_sync(0xffffffffu, df, o);
                sf += __shfl_xor_sync(0xffffffffu, sf, o);
                dv += __shfl_xor_sync(0xffffffffu, dv, o);
                sv += __shfl_xor_sync(0xffffffffu, sv, o);
                dt += __shfl_xor_sync(0xffffffffu, dt, o);
                st += __shfl_xor_sync(0xffffffffu, st, o);
            }
            if (k8 == 0) {
                float dfh = df * rsqrtf(fmaxf(sf, 1e-24f));
                float dvh = dv * rsqrtf(fmaxf(sv, 1e-24f));
                float dth = dt * rsqrtf(fmaxf(st, 1e-24f));
                float cf = 2.f - 2.f * dfh;
                float cc = 2.f - 2.f * (dvh + dth);
                accRow += (double)(1.2f * cf + 0.5f * cc)
                        + (double)(1.2f * scostF[r] + 0.5f * scostC[r]) * (1.0 / 65536.0);
            }
            // NOTE: Y/X now hold next tile's gt_f/gt_v, matching the loop head.
        } else {
            // ---- slow path: exact fp32 commit (taken only if some W != I) ----
            for (int rr = w * 4; rr < w * 4 + 4; ++rr) {
                int row = tileRow + rr;
                int jf = skf[rr], jc = skc[rr];
                float cf = slow_commit(gs_f + (size_t)row * DIM, W_f, g_CnF + (size_t)jf * DIM, lane);
                float cv = slow_commit(gs_v + (size_t)row * DIM, W_v, g_CnV + (size_t)jc * DIM, lane);
                float ct = slow_commit(gs_t + (size_t)row * DIM, W_t, g_CnT + (size_t)jc * DIM, lane);
                if (lane == 0)
                    cmBuf[rr] = 1.2f * cf + 0.25f * cv + 0.25f * ct;
            }
            __syncthreads();
            if (tid < TILE_R) {
                accRow += (double)cmBuf[tid]
                        + (double)(1.2f * scostF[tid] + 0.5f * scostC[tid]) * (1.0 / 65536.0);
            }
            if (more) {
                ld_rows(gt_f, nt * TILE_R, r, k8, Y);
                ld_rows(gt_v, nt * TILE_R, r, k8, X);
            }
            __syncthreads();
        }
    }

    // ---- deterministic block reduction, then single-atomic global finish ----
    red[tid] = accRow;
    __syncthreads();
    if (tid == 0) {
        double s = 0.0;
        for (int i = 0; i < MTHREADS; ++i) s += red[i];
        atomicAdd(&g_sum, s);
        __threadfence();
        unsigned old = atomicInc(&g_count, NBLOCKS - 1);   // wraps to 0 at last block
        if (old == NBLOCKS - 1) {
            out[0] = (float)atomicAdd(&g_sum, 0.0);        // coherent read
        }
    }
}

// ---------------- launch ----------------
extern "C" void kernel_launch(void* const* d_in, const int* in_sizes, int n_in,
                              void* d_out, int out_size) {
    const float* gt_v = (const float*)d_in[0];
    const float* gt_t = (const float*)d_in[1];
    const float* gt_f = (const float*)d_in[2];
    const float* gs_v = (const float*)d_in[3];
    const float* gs_t = (const float*)d_in[4];
    const float* gs_f = (const float*)d_in[5];
    const float* W_v  = (const float*)d_in[6];
    const float* W_t  = (const float*)d_in[7];
    const float* W_f  = (const float*)d_in[8];
    const float* book_f = (const float*)d_in[9];
    const float* v_cent = (const float*)d_in[10];
    const float* t_cent = (const float*)d_in[11];
    float* out = (float*)d_out;

    cudaFuncSetAttribute(main_kernel, cudaFuncAttributeMaxDynamicSharedMemorySize,
                         SMEM_TOTAL);

    setup_all<<<960, 256>>>(book_f, v_cent, t_cent, W_v, W_t, W_f);
    main_kernel<<<NBLOCKS, MTHREADS, SMEM_TOTAL>>>(gt_v, gt_t, gt_f, gs_v, gs_t, gs_f,
                                                   W_v, W_t, W_f, out);
}